// round 12
// baseline (speedup 1.0000x reference)
#include <cuda_runtime.h>
#include <math.h>

#define N_PTS 12288
#define DIM   128
#define BI    32
#define BJ    32
#define TILES (N_PTS / BJ)   /* 384 */
#define EPSF  1e-7f
#define MAXN  (1.0f - 1e-3f)

// Scratch (device globals — no allocation allowed)
__device__ float  g_xt[N_PTS * DIM];   // logmap0(x), pre-rounded to tf32
__device__ float4 g_rw[N_PTS];         // per-row: (E1=e^wh1, F1=e^{0.2wh1}, Ethr=e^{-wh1}, 0)
__device__ float2 g_ef[N_PTS];         // per-col: (e2=e^wh2, f2=e^{0.2wh2})

__device__ __forceinline__ unsigned f2tf32(float f) {
    unsigned u;
    asm("cvt.rna.tf32.f32 %0, %1;" : "=r"(u) : "f"(f));
    return u;
}

// m16n8k8 tf32 MMA, fp32 accumulate
#define MMA_TF32(d, a0, a1, a2, a3, b0, b1)                                   \
    asm volatile(                                                             \
        "mma.sync.aligned.m16n8k8.row.col.f32.tf32.tf32.f32 "                 \
        "{%0,%1,%2,%3}, {%4,%5,%6,%7}, {%8,%9}, {%0,%1,%2,%3};"               \
        : "+f"(d[0]), "+f"(d[1]), "+f"(d[2]), "+f"(d[3])                      \
        : "r"(a0), "r"(a1), "r"(a2), "r"(a3), "r"(b0), "r"(b1))

#define CP16(dst, src) \
    asm volatile("cp.async.cg.shared.global [%0], [%1], 16;" :: "r"(dst), "l"(src))
#define CP_COMMIT() asm volatile("cp.async.commit_group;")
#define CP_WAIT2()  asm volatile("cp.async.wait_group 2;" ::: "memory")

// ---------------------------------------------------------------------------
// Kernel 1: logmap0 + wh projections; factor exp terms; store xt as tf32
// ---------------------------------------------------------------------------
__global__ void prep_kernel(const float* __restrict__ x, const float* __restrict__ a) {
    int i = blockIdx.x;
    int d = threadIdx.x;
    float xv = x[(size_t)i * DIM + d];
    float s0 = xv * xv;
    float s1 = xv * a[d];
    float s2 = xv * a[DIM + d];
#pragma unroll
    for (int o = 16; o > 0; o >>= 1) {
        s0 += __shfl_down_sync(0xffffffffu, s0, o);
        s1 += __shfl_down_sync(0xffffffffu, s1, o);
        s2 += __shfl_down_sync(0xffffffffu, s2, o);
    }
    __shared__ float sm0[4], sm1[4], sm2[4];
    __shared__ float sscale;
    int w = d >> 5, l = d & 31;
    if (l == 0) { sm0[w] = s0; sm1[w] = s1; sm2[w] = s2; }
    __syncthreads();
    if (d == 0) {
        float t0 = sm0[0] + sm0[1] + sm0[2] + sm0[3];
        float t1 = sm1[0] + sm1[1] + sm1[2] + sm1[3];
        float t2 = sm2[0] + sm2[1] + sm2[2] + sm2[3];
        float n  = sqrtf(t0);
        float nc = fminf(fmaxf(n, EPSF), 1.0f - EPSF);
        float sc = atanhf(nc) / nc;
        sscale   = sc;
        float wh1 = sc * t1, wh2 = sc * t2;
        g_rw[i] = make_float4(expf(wh1), expf(0.2f * wh1), expf(-wh1), 0.f);
        g_ef[i] = make_float2(expf(wh2), expf(0.2f * wh2));
    }
    __syncthreads();
    g_xt[(size_t)i * DIM + d] = __uint_as_float(f2tf32(xv * sscale));
}

// ---------------------------------------------------------------------------
// Kernel 2: fused masked attention; depth-2 cp.async pipeline, 1 sync/tile.
// Body order: p(t) -> mma(t-1) -> issue X_t,A_t -> wait_group 2 -> sync.
// Rings: xt 3-buf (t%3), adj/ef 3-buf (t%3), pT 2-buf (t&1).
// ---------------------------------------------------------------------------
__global__ __launch_bounds__(256, 3) void attn_kernel(const int* __restrict__ adj,
                                                      float* __restrict__ out) {
    __shared__ __align__(16) float xt_s[3][BJ][132];   // 50.7 KB, tf32, j-permuted rows
    __shared__ __align__(16) float pTs[2][BI][34];     // 8.7 KB, tf32, j-permuted cols
    __shared__ __align__(16) int   adj_s[3][BI][BJ];   // 12.3 KB
    __shared__ __align__(16) float2 ef_s[3][BJ];       // 768 B
    __shared__ float l_s[BI];

    const int tid  = threadIdx.x;
    const int i0   = blockIdx.x * BI;
    const int lane = tid & 31, w = tid >> 5;
    const int g    = lane >> 2, tig = lane & 3;
    const int m0   = (w & 1) << 4;
    const int sl   = (w >> 1) << 5;
    const int colb = sl + (g << 2);
    const int p_row = tid >> 3, p_jo = tid & 7;   // thread owns js 4*p_jo..4*p_jo+3
    // permuted pT store base: j=4*jo+m -> col 8*(jo>>1) + 2m + (jo&1)
    const int pst = ((p_jo >> 1) << 3) + (p_jo & 1);

    float acc[4][4];
#pragma unroll
    for (int nt = 0; nt < 4; nt++)
#pragma unroll
        for (int c = 0; c < 4; c++) acc[nt][c] = 0.f;

    // cp.async destination/source offsets
    unsigned xtb = (unsigned)__cvta_generic_to_shared(&xt_s[0][0][0]);
    unsigned ajb = (unsigned)__cvta_generic_to_shared(&adj_s[0][0][0]);
    unsigned efb = (unsigned)__cvta_generic_to_shared(&ef_s[0][0]);
    unsigned xdoff[4]; int xsoff[4];
#pragma unroll
    for (int s = 0; s < 4; s++) {
        int slot = tid + (s << 8);
        int jn = slot >> 5;                 // 0..31
        int c4 = (slot & 31) << 2;
        int r7 = jn & 7;
        int lr = (jn & ~7) + ((r7 & 3) << 1) + (r7 >> 2);
        xdoff[s] = (unsigned)((lr * 132 + c4) << 2);
        xsoff[s] = jn * DIM + c4;
    }
    const int arow = tid >> 3, aj4 = (tid & 7) << 2;           // adj chunk
    const unsigned adoff = (unsigned)((arow * BJ + aj4) << 2);

    const float4 rw = g_rw[i0 + p_row];
    const float E1 = rw.x, F1 = rw.y, Ethr = rw.z;
    const int* adjr = adj + (size_t)(i0 + arow) * N_PTS;

    // ---- prologue: groups A_{-2}={adj0,ef0}, X_{-1}={xt0}, A_{-1}={adj1,ef1} ----
    CP16(ajb + 0 * (BI * BJ * 4) + adoff, adjr + aj4);
    if (tid < 16) CP16(efb + 0 * (BJ * 8) + tid * 16, g_ef + tid * 2);
    CP_COMMIT();
#pragma unroll
    for (int s = 0; s < 4; s++) CP16(xtb + 0 * (BJ * 132 * 4) + xdoff[s], g_xt + xsoff[s]);
    CP_COMMIT();
    CP16(ajb + 1 * (BI * BJ * 4) + adoff, adjr + BJ + aj4);
    if (tid < 16) CP16(efb + 1 * (BJ * 8) + tid * 16, g_ef + BJ + tid * 2);
    CP_COMMIT();
    CP_WAIT2();
    __syncthreads();

    float lsum = 0.f;
    int b3 = 0;  // t % 3

    for (int t = 0; t < TILES; t++) {
        const int b2 = t & 1;
        const int w3 = (b3 + 2) % 3;   // ring slot for tile t+2 (and xt t+1 uses (b3+1)%3)

        // ---- p-compute(t): adj via one LDS.128, ef broadcast ----
        {
            const int4 av = *(const int4*)&adj_s[b3][p_row][p_jo << 2];
            const float4 efa = *(const float4*)&ef_s[b3][p_jo << 2];      // j, j+1
            const float4 efb2 = *(const float4*)&ef_s[b3][(p_jo << 2) + 2]; // j+2, j+3
            float* ps = &pTs[b2][p_row][pst];
            float p0 = (av.x > 0) ? ((efa.x  >= Ethr) ? E1 * efa.x  : F1 * efa.y)  : 0.f;
            float p1 = (av.y > 0) ? ((efa.z  >= Ethr) ? E1 * efa.z  : F1 * efa.w)  : 0.f;
            float p2 = (av.z > 0) ? ((efb2.x >= Ethr) ? E1 * efb2.x : F1 * efb2.y) : 0.f;
            float p3 = (av.w > 0) ? ((efb2.z >= Ethr) ? E1 * efb2.z : F1 * efb2.w) : 0.f;
            p0 = __uint_as_float(f2tf32(p0));
            p1 = __uint_as_float(f2tf32(p1));
            p2 = __uint_as_float(f2tf32(p2));
            p3 = __uint_as_float(f2tf32(p3));
            ps[0] = p0; ps[2] = p1; ps[4] = p2; ps[6] = p3;
            lsum += (p0 + p1) + (p2 + p3);
        }

        // ---- mma(t-1) ----
        if (t > 0) {
            const int pm = (t - 1) % 3;
            const float (*xs)[132] = xt_s[pm];
            const float (*pp)[34]  = pTs[(t - 1) & 1];
#pragma unroll
            for (int s = 0; s < 4; s++) {
                int lr = (s << 3) + (tig << 1);
                float2 pa0 = *(const float2*)&pp[m0 + g][lr];
                float2 pa1 = *(const float2*)&pp[m0 + 8 + g][lr];
                uint4  xb0 = *(const uint4*)&xs[lr][colb];
                uint4  xb1 = *(const uint4*)&xs[lr + 1][colb];
                unsigned a0 = __float_as_uint(pa0.x), a1 = __float_as_uint(pa1.x);
                unsigned a2 = __float_as_uint(pa0.y), a3 = __float_as_uint(pa1.y);
                MMA_TF32(acc[0], a0, a1, a2, a3, xb0.x, xb1.x);
                MMA_TF32(acc[1], a0, a1, a2, a3, xb0.y, xb1.y);
                MMA_TF32(acc[2], a0, a1, a2, a3, xb0.z, xb1.z);
                MMA_TF32(acc[3], a0, a1, a2, a3, xb0.w, xb1.w);
            }
        }

        // ---- issue X_t = {xt(t+1)} ----
        if (t + 1 < TILES) {
            const float* srcb = g_xt + (size_t)(t + 1) * BJ * DIM;
            unsigned base = xtb + ((b3 + 1) % 3) * (BJ * 132 * 4);
#pragma unroll
            for (int s = 0; s < 4; s++) CP16(base + xdoff[s], srcb + xsoff[s]);
        }
        CP_COMMIT();
        // ---- issue A_t = {adj(t+2), ef(t+2)} ----
        if (t + 2 < TILES) {
            CP16(ajb + w3 * (BI * BJ * 4) + adoff, adjr + (t + 2) * BJ + aj4);
            if (tid < 16) CP16(efb + w3 * (BJ * 8) + tid * 16,
                               g_ef + (t + 2) * BJ + tid * 2);
        }
        CP_COMMIT();

        CP_WAIT2();
        __syncthreads();

        b3 = (b3 + 1) % 3;
    }

    // ---- epilogue mma(TILES-1) ----
    {
        const float (*xs)[132] = xt_s[(TILES - 1) % 3];
        const float (*pp)[34]  = pTs[(TILES - 1) & 1];
#pragma unroll
        for (int s = 0; s < 4; s++) {
            int lr = (s << 3) + (tig << 1);
            float2 pa0 = *(const float2*)&pp[m0 + g][lr];
            float2 pa1 = *(const float2*)&pp[m0 + 8 + g][lr];
            uint4  xb0 = *(const uint4*)&xs[lr][colb];
            uint4  xb1 = *(const uint4*)&xs[lr + 1][colb];
            unsigned a0 = __float_as_uint(pa0.x), a1 = __float_as_uint(pa1.x);
            unsigned a2 = __float_as_uint(pa0.y), a3 = __float_as_uint(pa1.y);
            MMA_TF32(acc[0], a0, a1, a2, a3, xb0.x, xb1.x);
            MMA_TF32(acc[1], a0, a1, a2, a3, xb0.y, xb1.y);
            MMA_TF32(acc[2], a0, a1, a2, a3, xb0.z, xb1.z);
            MMA_TF32(acc[3], a0, a1, a2, a3, xb0.w, xb1.w);
        }
    }

    // ---- finalize l ----
    lsum += __shfl_xor_sync(0xffffffffu, lsum, 1);
    lsum += __shfl_xor_sync(0xffffffffu, lsum, 2);
    lsum += __shfl_xor_sync(0xffffffffu, lsum, 4);
    if ((lane & 7) == 0) l_s[p_row] = lsum;

    // ---- scatter accumulators into xt_s[0] (buffer 0; last mma used buffer 2) ----
#pragma unroll
    for (int nt = 0; nt < 4; nt++) {
        xt_s[0][m0 + g][sl + (tig << 3) + nt]         = acc[nt][0];
        xt_s[0][m0 + g][sl + (tig << 3) + 4 + nt]     = acc[nt][1];
        xt_s[0][m0 + 8 + g][sl + (tig << 3) + nt]     = acc[nt][2];
        xt_s[0][m0 + 8 + g][sl + (tig << 3) + 4 + nt] = acc[nt][3];
    }
    __syncthreads();

    // ---- epilogue: v = acc/l; expmap0; proj ----
    {
        int cx = lane;
#pragma unroll
        for (int r = 0; r < 4; r++) {
            int row = (w << 2) + r;
            float linv = 1.f / l_s[row];
            float4 v = *(const float4*)&xt_s[0][row][cx << 2];
            float v0 = v.x * linv, v1 = v.y * linv;
            float v2 = v.z * linv, v3 = v.w * linv;
            float part = v0 * v0 + v1 * v1 + v2 * v2 + v3 * v3;
#pragma unroll
            for (int o2 = 16; o2 > 0; o2 >>= 1)
                part += __shfl_xor_sync(0xffffffffu, part, o2);
            float n  = sqrtf(part);
            float nc = fmaxf(n, EPSF);
            float sc = tanhf(nc) / nc;            // expmap0 scale
            float ny = fmaxf(sc * n, EPSF);       // ||y||
            float f  = (ny > MAXN) ? sc * (MAXN / ny) : sc;  // proj
            *(float4*)&out[(size_t)(i0 + row) * DIM + (cx << 2)] =
                make_float4(v0 * f, v1 * f, v2 * f, v3 * f);
        }
    }
}

// ---------------------------------------------------------------------------
extern "C" void kernel_launch(void* const* d_in, const int* in_sizes, int n_in,
                              void* d_out, int out_size) {
    const float* x = nullptr;
    const int*   adj = nullptr;
    const float* a = nullptr;
    for (int i = 0; i < n_in; i++) {
        if (in_sizes[i] == N_PTS * DIM)      x   = (const float*)d_in[i];
        else if (in_sizes[i] == 2 * DIM)     a   = (const float*)d_in[i];
        else                                 adj = (const int*)d_in[i];
    }
    float* out = (float*)d_out;

    prep_kernel<<<N_PTS, DIM>>>(x, a);
    attn_kernel<<<N_PTS / BI, 256>>>(adj, out);
}

// round 14
// speedup vs baseline: 1.1105x; 1.1105x over previous
#include <cuda_runtime.h>
#include <math.h>

#define N_PTS 12288
#define DIM   128
#define BI    32
#define BJ    48
#define TILES (N_PTS / BJ)   /* 256 */
#define BWORDS (N_PTS / 32)  /* 384 words per bitmap row */
#define EPSF  1e-7f
#define MAXN  (1.0f - 1e-3f)

// Scratch (device globals — no allocation allowed)
__device__ float    g_xt[N_PTS * DIM];        // logmap0(x), pre-rounded to tf32
__device__ float4   g_rw[N_PTS];              // per-row: (E1=e^wh1, F1=e^{0.2wh1}, Ethr=e^{-wh1}, 0)
__device__ float2   g_ef[N_PTS];              // per-col: (e2=e^wh2, f2=e^{0.2wh2})
__device__ unsigned g_bm[N_PTS * BWORDS + 32]; // adj bitmask, 18.9 MB (+pad)

__device__ __forceinline__ unsigned f2tf32(float f) {
    unsigned u;
    asm("cvt.rna.tf32.f32 %0, %1;" : "=r"(u) : "f"(f));
    return u;
}

// m16n8k8 tf32 MMA, fp32 accumulate
#define MMA_TF32(d, a0, a1, a2, a3, b0, b1)                                   \
    asm volatile(                                                             \
        "mma.sync.aligned.m16n8k8.row.col.f32.tf32.tf32.f32 "                 \
        "{%0,%1,%2,%3}, {%4,%5,%6,%7}, {%8,%9}, {%0,%1,%2,%3};"               \
        : "+f"(d[0]), "+f"(d[1]), "+f"(d[2]), "+f"(d[3])                      \
        : "r"(a0), "r"(a1), "r"(a2), "r"(a3), "r"(b0), "r"(b1))

#define CP16(dst, src) \
    asm volatile("cp.async.cg.shared.global [%0], [%1], 16;" :: "r"(dst), "l"(src))
#define CP_COMMIT() asm volatile("cp.async.commit_group;")
#define CP_WAIT0()  asm volatile("cp.async.wait_group 0;" ::: "memory")

// ---------------------------------------------------------------------------
// Kernel 0: pack adj (int32 0/1) -> bitmask. One warp produces 8 words/iter.
// Fully coalesced 128B reads; ~604 MB streamed once.
// ---------------------------------------------------------------------------
__global__ void pack_kernel(const int* __restrict__ adj) {
    unsigned warp_g = (blockIdx.x * blockDim.x + threadIdx.x) >> 5;
    int lane = threadIdx.x & 31;
    size_t base_word = (size_t)warp_g * 8;
    const int* src = adj + base_word * 32 + lane;
#pragma unroll
    for (int k = 0; k < 8; k++) {
        int v = src[k * 32];
        unsigned m = __ballot_sync(0xffffffffu, v > 0);
        if (lane == 0) g_bm[base_word + k] = m;
    }
}

// ---------------------------------------------------------------------------
// Kernel 1: logmap0 + wh projections; factor exp terms; store xt as tf32
// ---------------------------------------------------------------------------
__global__ void prep_kernel(const float* __restrict__ x, const float* __restrict__ a) {
    int i = blockIdx.x;
    int d = threadIdx.x;
    float xv = x[(size_t)i * DIM + d];
    float s0 = xv * xv;
    float s1 = xv * a[d];
    float s2 = xv * a[DIM + d];
#pragma unroll
    for (int o = 16; o > 0; o >>= 1) {
        s0 += __shfl_down_sync(0xffffffffu, s0, o);
        s1 += __shfl_down_sync(0xffffffffu, s1, o);
        s2 += __shfl_down_sync(0xffffffffu, s2, o);
    }
    __shared__ float sm0[4], sm1[4], sm2[4];
    __shared__ float sscale;
    int w = d >> 5, l = d & 31;
    if (l == 0) { sm0[w] = s0; sm1[w] = s1; sm2[w] = s2; }
    __syncthreads();
    if (d == 0) {
        float t0 = sm0[0] + sm0[1] + sm0[2] + sm0[3];
        float t1 = sm1[0] + sm1[1] + sm1[2] + sm1[3];
        float t2 = sm2[0] + sm2[1] + sm2[2] + sm2[3];
        float n  = sqrtf(t0);
        float nc = fminf(fmaxf(n, EPSF), 1.0f - EPSF);
        float sc = atanhf(nc) / nc;
        sscale   = sc;
        float wh1 = sc * t1, wh2 = sc * t2;
        g_rw[i] = make_float4(expf(wh1), expf(0.2f * wh1), expf(-wh1), 0.f);
        g_ef[i] = make_float2(expf(wh2), expf(0.2f * wh2));
    }
    __syncthreads();
    g_xt[(size_t)i * DIM + d] = __uint_as_float(f2tf32(xv * sscale));
}

// ---------------------------------------------------------------------------
// Kernel 2: fused masked attention via bitmask; 1 cp.async group + 1 sync/tile.
// Body: p(t)[regs] -> wait xt(t) -> sync -> issue xt(t+1) -> prefetch bm/ef -> mma(t).
// Thread (p_row=tid/8, p_jo=tid%8) owns js [6*p_jo, 6*p_jo+6) of each tile.
// ---------------------------------------------------------------------------
__global__ __launch_bounds__(256, 3) void attn_kernel(float* __restrict__ out) {
    __shared__ __align__(16) float xt_s[2][BJ][132];  // 50.7 KB, tf32, j-permuted rows
    __shared__ __align__(16) float pTs[2][BI][56];    // 14.3 KB, tf32, j-permuted cols
    __shared__ float l_s[BI];

    const int tid  = threadIdx.x;
    const int i0   = blockIdx.x * BI;
    const int lane = tid & 31, w = tid >> 5;
    const int g    = lane >> 2, tig = lane & 3;
    const int m0   = (w & 1) << 4;
    const int sl   = (w >> 1) << 5;
    const int colb = sl + (g << 2);
    const int p_row = tid >> 3, p_jo = tid & 7;

    // permuted pT store columns for j = 6*p_jo + k (within-tile)
    int pcol[6];
#pragma unroll
    for (int k = 0; k < 6; k++) {
        int jj = 6 * p_jo + k;
        pcol[k] = ((jj >> 3) << 3) + ((jj & 3) << 1) + ((jj & 7) >> 2);
    }

    float acc[4][4];
#pragma unroll
    for (int nt = 0; nt < 4; nt++)
#pragma unroll
        for (int c = 0; c < 4; c++) acc[nt][c] = 0.f;

    // cp.async offsets (6 x 16B per thread per tile), j-permuted rows
    unsigned xtb[2];
    xtb[0] = (unsigned)__cvta_generic_to_shared(&xt_s[0][0][0]);
    xtb[1] = (unsigned)__cvta_generic_to_shared(&xt_s[1][0][0]);
    unsigned xdoff[6]; int xsoff[6];
#pragma unroll
    for (int s = 0; s < 6; s++) {
        int slot = tid + (s << 8);
        int jn = slot >> 5;
        int c4 = (slot & 31) << 2;
        int r7 = jn & 7;
        int lr = (jn & ~7) + ((r7 & 3) << 1) + (r7 >> 2);
        xdoff[s] = (unsigned)((lr * 132 + c4) << 2);
        xsoff[s] = jn * DIM + c4;
    }

    const float4 rw = g_rw[i0 + p_row];
    const float E1 = rw.x, F1 = rw.y, Ethr = rw.z;
    const unsigned* rowbm = g_bm + (size_t)(i0 + p_row) * BWORDS;

    // ---- prologue: issue xt(0); prefetch bm/ef for tile 0 ----
#pragma unroll
    for (int s = 0; s < 6; s++) CP16(xtb[0] + xdoff[s], g_xt + xsoff[s]);
    CP_COMMIT();
    unsigned bmA, bmB;
    float4 e01, e23, e45;
    {
        int j0 = 6 * p_jo;
        bmA = __ldg(rowbm + (j0 >> 5));
        bmB = __ldg(rowbm + (j0 >> 5) + 1);
        const float4* efp = (const float4*)(g_ef + j0);
        e01 = efp[0]; e23 = efp[1]; e45 = efp[2];
    }

    float lsum = 0.f;

    for (int t = 0; t < TILES; t++) {
        const int b = t & 1;

        // ---- p-compute(t): 6 bits from funnel-shifted window ----
        {
            int j0 = t * BJ + 6 * p_jo;
            unsigned win = __funnelshift_r(bmA, bmB, j0 & 31);
            float p0 = (win & 1u)  ? ((e01.x >= Ethr) ? E1 * e01.x : F1 * e01.y) : 0.f;
            float p1 = (win & 2u)  ? ((e01.z >= Ethr) ? E1 * e01.z : F1 * e01.w) : 0.f;
            float p2 = (win & 4u)  ? ((e23.x >= Ethr) ? E1 * e23.x : F1 * e23.y) : 0.f;
            float p3 = (win & 8u)  ? ((e23.z >= Ethr) ? E1 * e23.z : F1 * e23.w) : 0.f;
            float p4 = (win & 16u) ? ((e45.x >= Ethr) ? E1 * e45.x : F1 * e45.y) : 0.f;
            float p5 = (win & 32u) ? ((e45.z >= Ethr) ? E1 * e45.z : F1 * e45.w) : 0.f;
            p0 = __uint_as_float(f2tf32(p0));
            p1 = __uint_as_float(f2tf32(p1));
            p2 = __uint_as_float(f2tf32(p2));
            p3 = __uint_as_float(f2tf32(p3));
            p4 = __uint_as_float(f2tf32(p4));
            p5 = __uint_as_float(f2tf32(p5));
            float* ps = &pTs[b][p_row][0];
            ps[pcol[0]] = p0; ps[pcol[1]] = p1; ps[pcol[2]] = p2;
            ps[pcol[3]] = p3; ps[pcol[4]] = p4; ps[pcol[5]] = p5;
            lsum += ((p0 + p1) + (p2 + p3)) + (p4 + p5);
        }

        CP_WAIT0();            // xt(t) resident
        __syncthreads();       // pT(t) visible; xt buffer b^1 free

        // ---- issue xt(t+1); prefetch bm/ef(t+1) (hidden by mma) ----
        if (t + 1 < TILES) {
            const float* srcb = g_xt + (size_t)(t + 1) * BJ * DIM;
            unsigned base = xtb[b ^ 1];
#pragma unroll
            for (int s = 0; s < 6; s++) CP16(base + xdoff[s], srcb + xsoff[s]);
            CP_COMMIT();
            int j0n = (t + 1) * BJ + 6 * p_jo;
            bmA = __ldg(rowbm + (j0n >> 5));
            bmB = __ldg(rowbm + (j0n >> 5) + 1);
            const float4* efp = (const float4*)(g_ef + j0n);
            e01 = efp[0]; e23 = efp[1]; e45 = efp[2];
        }

        // ---- mma(t): 24 tf32 MMAs per warp ----
        {
            const float (*xs)[132] = xt_s[b];
            const float (*pp)[56]  = pTs[b];
#pragma unroll
            for (int s = 0; s < 6; s++) {
                int lr = (s << 3) + (tig << 1);
                float2 pa0 = *(const float2*)&pp[m0 + g][lr];
                float2 pa1 = *(const float2*)&pp[m0 + 8 + g][lr];
                uint4  xb0 = *(const uint4*)&xs[lr][colb];
                uint4  xb1 = *(const uint4*)&xs[lr + 1][colb];
                unsigned a0 = __float_as_uint(pa0.x), a1 = __float_as_uint(pa1.x);
                unsigned a2 = __float_as_uint(pa0.y), a3 = __float_as_uint(pa1.y);
                MMA_TF32(acc[0], a0, a1, a2, a3, xb0.x, xb1.x);
                MMA_TF32(acc[1], a0, a1, a2, a3, xb0.y, xb1.y);
                MMA_TF32(acc[2], a0, a1, a2, a3, xb0.z, xb1.z);
                MMA_TF32(acc[3], a0, a1, a2, a3, xb0.w, xb1.w);
            }
        }
    }

    // ---- finalize l (8 lanes per row within warp) ----
    lsum += __shfl_xor_sync(0xffffffffu, lsum, 1);
    lsum += __shfl_xor_sync(0xffffffffu, lsum, 2);
    lsum += __shfl_xor_sync(0xffffffffu, lsum, 4);
    if ((lane & 7) == 0) l_s[p_row] = lsum;

    // ---- scatter accumulators into xt_s[0] (unpermuted cols) ----
#pragma unroll
    for (int nt = 0; nt < 4; nt++) {
        xt_s[0][m0 + g][sl + (tig << 3) + nt]         = acc[nt][0];
        xt_s[0][m0 + g][sl + (tig << 3) + 4 + nt]     = acc[nt][1];
        xt_s[0][m0 + 8 + g][sl + (tig << 3) + nt]     = acc[nt][2];
        xt_s[0][m0 + 8 + g][sl + (tig << 3) + 4 + nt] = acc[nt][3];
    }
    __syncthreads();

    // ---- epilogue: v = acc/l; expmap0; proj ----
    {
        int cx = lane;
#pragma unroll
        for (int r = 0; r < 4; r++) {
            int row = (w << 2) + r;
            float linv = 1.f / l_s[row];
            float4 v = *(const float4*)&xt_s[0][row][cx << 2];
            float v0 = v.x * linv, v1 = v.y * linv;
            float v2 = v.z * linv, v3 = v.w * linv;
            float part = v0 * v0 + v1 * v1 + v2 * v2 + v3 * v3;
#pragma unroll
            for (int o2 = 16; o2 > 0; o2 >>= 1)
                part += __shfl_xor_sync(0xffffffffu, part, o2);
            float n  = sqrtf(part);
            float nc = fmaxf(n, EPSF);
            float sc = tanhf(nc) / nc;            // expmap0 scale
            float ny = fmaxf(sc * n, EPSF);       // ||y||
            float f  = (ny > MAXN) ? sc * (MAXN / ny) : sc;  // proj
            *(float4*)&out[(size_t)(i0 + row) * DIM + (cx << 2)] =
                make_float4(v0 * f, v1 * f, v2 * f, v3 * f);
        }
    }
}

// ---------------------------------------------------------------------------
extern "C" void kernel_launch(void* const* d_in, const int* in_sizes, int n_in,
                              void* d_out, int out_size) {
    const float* x = nullptr;
    const int*   adj = nullptr;
    const float* a = nullptr;
    for (int i = 0; i < n_in; i++) {
        if (in_sizes[i] == N_PTS * DIM)      x   = (const float*)d_in[i];
        else if (in_sizes[i] == 2 * DIM)     a   = (const float*)d_in[i];
        else                                 adj = (const int*)d_in[i];
    }
    float* out = (float*)d_out;

    // words total = N*N/32 = 4,718,592; 64 words per 256-thread block
    pack_kernel<<<(N_PTS * (N_PTS / 32)) / 64, 256>>>(adj);
    prep_kernel<<<N_PTS, DIM>>>(x, a);
    attn_kernel<<<N_PTS / BI, 256>>>(out);
}